// round 2
// baseline (speedup 1.0000x reference)
#include <cuda_runtime.h>

// Fixed problem shapes (SpanRepresentation_32487132627590)
#define BATCH   4
#define SLEN    2048
#define DIM     768
#define NSPAN   4096
#define CHUNK   64
#define NCHUNK  (SLEN / CHUNK)          // 32
#define OUTW    2364                    // 768*3 + 20*3
// segment offsets in each output row (all divisible by 4 -> float4 stores)
#define OFF_MEAN 0
#define OFF_XS0  768
#define OFF_P0   1536
#define OFF_XS1  1556
#define OFF_P1   2324
#define OFF_W    2344

// Scratch: exclusive prefix sums cs[b, s, d], s in [0, SLEN]  (~25.2 MB)
__device__ float g_cs[(size_t)BATCH * (SLEN + 1) * DIM];
// Per-chunk sums chunk[b, c, d]
__device__ float g_chunk[(size_t)BATCH * NCHUNK * DIM];

// ---------------------------------------------------------------------------
// Kernel 1: partial sums per (b, chunk, d).  grid = BATCH*NCHUNK, block = DIM
// ---------------------------------------------------------------------------
__global__ void chunksum_kernel(const float* __restrict__ x) {
    const int d  = threadIdx.x;            // 0..767
    const int bc = blockIdx.x;             // b*NCHUNK + c
    const float* p = x + (size_t)bc * CHUNK * DIM + d;

    float a0 = 0.f, a1 = 0.f, a2 = 0.f, a3 = 0.f;
    #pragma unroll
    for (int i = 0; i < CHUNK; i += 4) {
        a0 += p[(size_t)(i + 0) * DIM];
        a1 += p[(size_t)(i + 1) * DIM];
        a2 += p[(size_t)(i + 2) * DIM];
        a3 += p[(size_t)(i + 3) * DIM];
    }
    g_chunk[(size_t)bc * DIM + d] = (a0 + a1) + (a2 + a3);
}

// ---------------------------------------------------------------------------
// Kernel 2: sequential in-chunk scan -> cs.  grid = BATCH*NCHUNK, block = DIM
// ---------------------------------------------------------------------------
__global__ void scan_write_kernel(const float* __restrict__ x) {
    const int d  = threadIdx.x;
    const int bc = blockIdx.x;
    const int b  = bc / NCHUNK;
    const int c  = bc % NCHUNK;

    // exclusive prefix of chunk sums
    float run = 0.f;
    const float* ch = g_chunk + (size_t)b * NCHUNK * DIM + d;
    for (int cc = 0; cc < c; cc++) run += ch[(size_t)cc * DIM];

    const float* p = x    + ((size_t)b * SLEN       + (size_t)c * CHUNK) * DIM + d;
    float*       q = g_cs + ((size_t)b * (SLEN + 1) + (size_t)c * CHUNK) * DIM + d;

    #pragma unroll 4
    for (int i = 0; i < CHUNK; i++) {
        q[(size_t)i * DIM] = run;           // cs[s] = exclusive prefix
        run += p[(size_t)i * DIM];
    }
    if (c == NCHUNK - 1) q[(size_t)CHUNK * DIM] = run;   // cs[SLEN]
}

// ---------------------------------------------------------------------------
// Kernel 3: one block per (b, n) output row.  block = 192 threads (768/4)
// ---------------------------------------------------------------------------
__global__ __launch_bounds__(192)
void span_kernel(const float* __restrict__ x,
                 const int* __restrict__ spans,
                 const int* __restrict__ pt_labels,
                 const float* __restrict__ wtab,
                 const float* __restrict__ ptab,
                 float* __restrict__ out) {
    const int bn = blockIdx.x;              // b*NSPAN + n
    const int b  = bn >> 12;                // / 4096
    const int n  = bn & (NSPAN - 1);
    const int t  = threadIdx.x;             // 0..191

    const int i0 = spans[2 * n + 0];
    const int i1 = spans[2 * n + 1];
    const int width = i1 - i0 + 1;

    // em = searchsorted(bins, width, 'right') - 1 = last bin <= width
    const int bins[16] = {0,1,2,3,4,5,7,8,9,10,15,16,31,32,63,64};
    int em = 0;
    #pragma unroll
    for (int i = 1; i < 16; i++) em = (width >= bins[i]) ? i : em;

    const int l0 = pt_labels[i0];
    const int l1 = pt_labels[i1];
    const float inv_w = 1.0f / (float)width;

    const float4* cs0 = (const float4*)(g_cs + ((size_t)b * (SLEN + 1) + i0    ) * DIM);
    const float4* cs1 = (const float4*)(g_cs + ((size_t)b * (SLEN + 1) + i1 + 1) * DIM);
    const float4* x0  = (const float4*)(x    + ((size_t)b * SLEN + i0) * DIM);
    const float4* x1  = (const float4*)(x    + ((size_t)b * SLEN + i1) * DIM);
    float* orow = out + (size_t)bn * OUTW;

    // mean (768), xs0 (768), xs1 (768): 192 float4 each, one per thread
    float4 a  = cs0[t];
    float4 bb = cs1[t];
    float4 m;
    m.x = (bb.x - a.x) * inv_w;
    m.y = (bb.y - a.y) * inv_w;
    m.z = (bb.z - a.z) * inv_w;
    m.w = (bb.w - a.w) * inv_w;
    ((float4*)(orow + OFF_MEAN))[t] = m;
    ((float4*)(orow + OFF_XS0 ))[t] = x0[t];
    ((float4*)(orow + OFF_XS1 ))[t] = x1[t];

    // embeddings: 20 floats each = 5 float4, all 16B-aligned offsets
    if (t < 5) {
        ((float4*)(orow + OFF_P0))[t] = ((const float4*)(ptab + l0 * 20))[t];
        ((float4*)(orow + OFF_P1))[t] = ((const float4*)(ptab + l1 * 20))[t];
        ((float4*)(orow + OFF_W ))[t] = ((const float4*)(wtab + em * 20))[t];
    }
}

// ---------------------------------------------------------------------------
extern "C" void kernel_launch(void* const* d_in, const int* in_sizes, int n_in,
                              void* d_out, int out_size) {
    const float* x      = (const float*)d_in[0];
    const int*   spans  = (const int*)d_in[1];
    const int*   labels = (const int*)d_in[2];
    const float* wtab   = (const float*)d_in[3];
    const float* ptab   = (const float*)d_in[4];
    float*       out    = (float*)d_out;

    chunksum_kernel  <<<BATCH * NCHUNK, DIM>>>(x);
    scan_write_kernel<<<BATCH * NCHUNK, DIM>>>(x);
    span_kernel      <<<BATCH * NSPAN, 192>>>(x, spans, labels, wtab, ptab, out);
}